// round 8
// baseline (speedup 1.0000x reference)
#include <cuda_runtime.h>
#include <cuda_fp16.h>
#include <math.h>
#include <stdint.h>

#define B    16
#define C    128
#define HH   128
#define WW   128
#define HW   (HH*WW)
#define KK   9
#define KCH  32
#define NCHUNK (C/KCH)

// Scratch. g_midh layout: [b][h][c][w]  (slab per (b,h) is contiguous 128x128 fp16)
__device__ __half g_midh[(size_t)B*C*HW];
__device__ __half g_wh[C*C];               // conv weights fp16 [o][k]
__device__ float  g_att[B*C];              // CA attention
__device__ float  g_t[B*C];                // hidden MLP activations
__device__ float  g_hid[B*16];             // CA hidden activations

__device__ __forceinline__ float lrelu(float v) { return v > 0.f ? v : 0.1f*v; }

__device__ __forceinline__ void cp16(void* dst, const void* src) {
    uint32_t d = (uint32_t)__cvta_generic_to_shared(dst);
    asm volatile("cp.async.cg.shared.global [%0], [%1], 16;" :: "r"(d), "l"(src));
}
__device__ __forceinline__ void cp_commit() {
    asm volatile("cp.async.commit_group;");
}

__device__ __forceinline__ void ldmatrix_x4(uint32_t* r, const void* p) {
    uint32_t a = (uint32_t)__cvta_generic_to_shared(p);
    asm volatile("ldmatrix.sync.aligned.m8n8.x4.shared.b16 {%0,%1,%2,%3}, [%4];"
                 : "=r"(r[0]), "=r"(r[1]), "=r"(r[2]), "=r"(r[3]) : "r"(a));
}
__device__ __forceinline__ void ldmatrix_x2_t(uint32_t* r, const void* p) {
    uint32_t a = (uint32_t)__cvta_generic_to_shared(p);
    asm volatile("ldmatrix.sync.aligned.m8n8.x2.trans.shared.b16 {%0,%1}, [%2];"
                 : "=r"(r[0]), "=r"(r[1]) : "r"(a));
}
__device__ __forceinline__ void mma_f16(float* d, const uint32_t* a, const uint32_t* b) {
    asm volatile(
        "mma.sync.aligned.m16n8k16.row.col.f32.f16.f16.f32 "
        "{%0,%1,%2,%3}, {%4,%5,%6,%7}, {%8,%9}, {%0,%1,%2,%3};"
        : "+f"(d[0]), "+f"(d[1]), "+f"(d[2]), "+f"(d[3])
        : "r"(a[0]), "r"(a[1]), "r"(a[2]), "r"(a[3]), "r"(b[0]), "r"(b[1]));
}

// ---------------------------------------------------------------------------
// P1: one block per MLP output j (144 = 128 t-outputs + 16 CA-hidden).
// Each warp handles 2 batches. grid = 144, block = 256.
// ---------------------------------------------------------------------------
__global__ void prep1_kernel(const float* __restrict__ deg,
                             const float* __restrict__ w1,
                             const float* __restrict__ caw1)
{
    const int j    = blockIdx.x;
    const int tid  = threadIdx.x;
    const int wid  = tid >> 5;
    const int lane = tid & 31;

    __shared__ float sdeg[B][C];

    #pragma unroll
    for (int i = tid; i < B*C; i += 256)
        ((float*)sdeg)[i] = deg[i];
    __syncthreads();

    const float* wrow = (j < 128) ? (w1 + j*C) : (caw1 + (j-128)*C);
    float w[4];
    #pragma unroll
    for (int u = 0; u < 4; ++u) w[u] = wrow[lane*4 + u];

    #pragma unroll
    for (int rep = 0; rep < 2; ++rep) {
        const int b = wid + rep*8;
        float acc = 0.f;
        #pragma unroll
        for (int u = 0; u < 4; ++u) acc += sdeg[b][lane*4 + u]*w[u];
        #pragma unroll
        for (int s = 16; s > 0; s >>= 1) acc += __shfl_xor_sync(0xffffffffu, acc, s);
        if (lane == 0) {
            if (j < 128) g_t[b*C + j]        = lrelu(acc);
            else         g_hid[b*16 + j-128] = lrelu(acc);
        }
    }
}

// ---------------------------------------------------------------------------
// P1b: CA attention sigmoid + fp16 weight conversion. grid = B, block = 256.
// ---------------------------------------------------------------------------
__global__ void prep1b_kernel(const float* __restrict__ caw2,
                              const float* __restrict__ convw)
{
    const int b   = blockIdx.x;
    const int tid = threadIdx.x;

    __shared__ float shid[16];
    if (tid < 16) shid[tid] = g_hid[b*16 + tid];
    __syncthreads();

    if (tid < C) {
        float acc = 0.f;
        const float* wrow = caw2 + tid*16;
        #pragma unroll
        for (int r = 0; r < 16; ++r) acc += shid[r]*wrow[r];
        g_att[b*C + tid] = 1.f/(1.f + expf(-acc));
    }

    {
        const int base = b*1024 + tid*4;
        float4 v = *(const float4*)(convw + base);
        g_wh[base+0] = __float2half(v.x);
        g_wh[base+1] = __float2half(v.y);
        g_wh[base+2] = __float2half(v.z);
        g_wh[base+3] = __float2half(v.w);
    }
}

// ---------------------------------------------------------------------------
// dwconv (+ fused kernel-coefficient dots): one block per (b,c) plane.
// Output in [b][h][c][w] layout. grid = B*C, block = 256.
// ---------------------------------------------------------------------------
__global__ void dwconv_kernel(const float* __restrict__ x0,
                              const float* __restrict__ w2)
{
    const int bc   = blockIdx.x;
    const int b    = bc >> 7;
    const int c    = bc & 127;
    const int tid  = threadIdx.x;
    const int wid  = tid >> 5;
    const int lane = tid & 31;

    __shared__ float sk[9];
    __shared__ float st[C];

    if (tid < C) st[tid] = g_t[b*C + tid];
    __syncthreads();

    for (int j = wid; j < KK; j += 8) {
        const float* wrow = w2 + (size_t)(c*KK + j)*C;
        float acc = 0.f;
        #pragma unroll
        for (int u = 0; u < 4; ++u) {
            const int idx = lane*4 + u;
            acc += st[idx]*wrow[idx];
        }
        #pragma unroll
        for (int s = 16; s > 0; s >>= 1) acc += __shfl_xor_sync(0xffffffffu, acc, s);
        if (lane == 0) sk[j] = acc;
    }
    __syncthreads();

    float k[9];
    #pragma unroll
    for (int i = 0; i < 9; ++i) k[i] = sk[i];

    const float* __restrict__ src = x0 + (size_t)bc*HW;

    for (int p4 = tid*4; p4 < HW; p4 += 256*4) {
        const int h  = p4 >> 7;
        const int w0 = p4 & (WW-1);
        float a0 = 0.f, a1 = 0.f, a2 = 0.f, a3 = 0.f;

        #pragma unroll
        for (int kh = 0; kh < 3; ++kh) {
            const int hh = h + kh - 1;
            if (hh < 0 || hh >= HH) continue;
            const float* row = src + hh*WW;
            float4 cv = __ldcs((const float4*)(row + w0));
            float vl = (w0 > 0)    ? __ldcs(row + w0 - 1) : 0.f;
            float vr = (w0 < WW-4) ? __ldcs(row + w0 + 4) : 0.f;
            const float k0 = k[kh*3+0], k1 = k[kh*3+1], k2 = k[kh*3+2];
            a0 += k0*vl   + k1*cv.x + k2*cv.y;
            a1 += k0*cv.x + k1*cv.y + k2*cv.z;
            a2 += k0*cv.y + k1*cv.z + k2*cv.w;
            a3 += k0*cv.z + k1*cv.w + k2*vr;
        }
        __half2 h01 = __floats2half2_rn(lrelu(a0), lrelu(a1));
        __half2 h23 = __floats2half2_rn(lrelu(a2), lrelu(a3));
        uint2 pk;
        pk.x = *(uint32_t*)&h01;
        pk.y = *(uint32_t*)&h23;
        // [b][h][c][w] layout
        *(uint2*)(g_midh + ((size_t)(b*HH + h)*C + c)*WW + w0) = pk;
    }
}

// ---------------------------------------------------------------------------
// GEMM: A (full K) loaded once + 2-stage B, XOR-swizzled smem (48 KB static).
// Block tile 128x128, 8 warps of 64x32. grid = (HH, B), block = 256.
// mid slab for (b,h) is contiguous: [c][w] 128x128 fp16.
// ---------------------------------------------------------------------------
__global__ void __launch_bounds__(256, 2)
gemm_f16(const float* __restrict__ bias,
         const float* __restrict__ x0,
         float* __restrict__ out)
{
    __shared__ __align__(16) __half sA[C*128];       // [o][k], swizzled, 32 KB
    __shared__ __align__(16) __half sB[2][KCH*128];  // [k][p], swizzled, 2x8 KB

    const int b    = blockIdx.y;
    const int h    = blockIdx.x;
    const int tid  = threadIdx.x;
    const int wid  = tid >> 5;
    const int lane = tid & 31;
    const int g    = lane >> 2;
    const int tg   = lane & 3;
    const int wm0  = (wid >> 2) * 64;
    const int wn0  = (wid & 3) * 32;

    float d[4][4][4];
    #pragma unroll
    for (int mt = 0; mt < 4; ++mt)
        #pragma unroll
        for (int nt = 0; nt < 4; ++nt)
            #pragma unroll
            for (int r = 0; r < 4; ++r) d[mt][nt][r] = 0.f;

    // contiguous slab for this (b,h): [c][w]
    const __half* __restrict__ midb = g_midh + (size_t)(b*HH + h)*C*WW;

    // B chunk loader: 32 rows x 16 units(16B) -> 2 units/thread
    const int bk = tid >> 3;
    const int bu = (tid & 7) * 2;

#define LOAD_B(cc, st) do {                                                    \
        const __half* srcb = midb + (size_t)((cc)*KCH + bk)*WW;                \
        __half* dstb = &sB[st][bk*128];                                        \
        const int u0s = (bu    ) ^ (bk & 7);                                   \
        const int u1s = (bu + 1) ^ (bk & 7);                                   \
        cp16(dstb + u0s*8, srcb + (bu    )*8);                                 \
        cp16(dstb + u1s*8, srcb + (bu + 1)*8);                                 \
        cp_commit();                                                           \
    } while (0)

    // ---- prologue: full A (swizzled) + B chunk 0 in group 0, B1 in group 1 ----
    {
        const int ao = tid >> 1;            // 0..127
        const int ub = (tid & 1) * 8;       // unit base
        const __half* srca = g_wh + ao*C;
        __half* dsta = &sA[ao*128];
        #pragma unroll
        for (int i = 0; i < 8; ++i) {
            const int u  = ub + i;
            const int us = u ^ (ao & 7);
            cp16(dsta + us*8, srca + u*8);
        }
        // B chunk 0 (same commit group as A)
        const __half* srcb = midb + (size_t)bk*WW;
        __half* dstb = &sB[0][bk*128];
        cp16(dstb + ((bu  )^(bk&7))*8, srcb + bu*8);
        cp16(dstb + ((bu+1)^(bk&7))*8, srcb + (bu+1)*8);
        cp_commit();                        // group 0: A + B0
    }

    // ---- main loop: 2-stage B pipeline ----
    #pragma unroll
    for (int c = 0; c < NCHUNK; ++c) {
        const int st = c & 1;
        if (c + 1 < NCHUNK) {
            LOAD_B(c + 1, (c + 1) & 1);
            asm volatile("cp.async.wait_group 1;");
        } else {
            asm volatile("cp.async.wait_group 0;");
        }
        __syncthreads();

        #pragma unroll
        for (int ks = 0; ks < KCH; ks += 16) {
            const int kg = c*KCH + ks;
            uint32_t af[4][4];
            const int arow = lane & 15;
            const int au   = (kg >> 3) + (lane >> 4);   // 16B unit of A col
            #pragma unroll
            for (int mt = 0; mt < 4; ++mt) {
                const int r = wm0 + mt*16 + arow;
                ldmatrix_x4(af[mt], &sA[r*128 + ((au ^ (r & 7)) << 3)]);
            }

            uint32_t bf[4][2];
            const int brow = ks + (lane & 15);
            #pragma unroll
            for (int nt = 0; nt < 4; ++nt) {
                const int un = (wn0 + nt*8) >> 3;
                ldmatrix_x2_t(bf[nt], &sB[st][brow*128 + ((un ^ (brow & 7)) << 3)]);
            }

            #pragma unroll
            for (int mt = 0; mt < 4; ++mt)
                #pragma unroll
                for (int nt = 0; nt < 4; ++nt)
                    mma_f16(d[mt][nt], af[mt], bf[nt]);
        }
        __syncthreads();   // protect stage st before it is reloaded next iter
    }

    // ---- fused epilogue: bias + x0*att residual (streaming) ----
    const int pix0 = h * WW;
    #pragma unroll
    for (int mt = 0; mt < 4; ++mt) {
        #pragma unroll
        for (int half = 0; half < 2; ++half) {
            const int o  = wm0 + mt*16 + g + half*8;
            const float bo = bias[o];
            const float at = g_att[b*C + o];
            const float* __restrict__ xrow = x0  + ((size_t)(b*C + o))*HW + pix0;
            float* __restrict__       orow = out + ((size_t)(b*C + o))*HW + pix0;
            #pragma unroll
            for (int nt = 0; nt < 4; ++nt) {
                const int cc2 = wn0 + nt*8 + 2*tg;
                float2 xv = __ldcs((const float2*)(xrow + cc2));
                float2 ov;
                ov.x = d[mt][nt][half*2 + 0] + bo + xv.x*at;
                ov.y = d[mt][nt][half*2 + 1] + bo + xv.y*at;
                __stcs((float2*)(orow + cc2), ov);
            }
        }
    }
}

// ---------------------------------------------------------------------------
extern "C" void kernel_launch(void* const* d_in, const int* in_sizes, int n_in,
                              void* d_out, int out_size)
{
    const float* x0    = (const float*)d_in[0];
    const float* deg   = (const float*)d_in[1];
    const float* w1    = (const float*)d_in[2];
    const float* w2    = (const float*)d_in[3];
    const float* convw = (const float*)d_in[4];
    const float* convb = (const float*)d_in[5];
    const float* caw1  = (const float*)d_in[6];
    const float* caw2  = (const float*)d_in[7];
    float* out = (float*)d_out;

    prep1_kernel<<<144, 256>>>(deg, w1, caw1);
    prep1b_kernel<<<B, 256>>>(caw2, convw);
    dwconv_kernel<<<B*C, 256>>>(x0, w2);
    gemm_f16<<<dim3(HH, B), 256>>>(convb, x0, out);
}